// round 10
// baseline (speedup 1.0000x reference)
#include <cuda_runtime.h>
#include <cuda_bf16.h>
#include <cstdint>

// ---------------------------------------------------------------------------
// OrdinalPeakedCELoss — persistent double-buffered pipeline, v2.
//  R9 post-mortem: 39.4us, issue=78.7%, occ=56.9% (register-limited to 5
//  blocks at 47 regs). This version:
//   * __launch_bounds__(256,6): regs<=40 -> 6 blocks/SM, 888 persistent blocks
//   * tiles of 256 rows (20.6KB smem/block) so smem never limits occupancy
//   * per-class op diet: d=k-fy shared by |d|-1 and sat(1-d); h=e*c shared by
//     far-max (min(h,e)) and tail (fma(h,c^2)) — exact for integer distances
//   * one row per thread per tile; cp.async.bulk + mbarrier double buffer
//  Deterministic: fixed tile->block map, fixed order, last-block double sum.
// ---------------------------------------------------------------------------

#define KCLS 9
#define NTHREADS 256
#define TILE 256                        /* rows per tile, 1 row/thread */
#define NSTAGES 2
#define LOG_BYTES (TILE * KCLS * 4)     /* 9216 */
#define Y_BYTES   (TILE * 4)            /* 1024 */
#define TX_BYTES  (LOG_BYTES + Y_BYTES) /* 10240 */
#define NBLK 888                        /* 148 SMs x 6 resident blocks */

#define ALPHA_C       0.4f
#define W_FAR_C       7.0f
#define DELTA_FAR_C   0.15f
#define W_TAIL_C      9.0f
#define W_LPEAK_C     12.0f
#define PROB_MARGIN_C 0.35f
#define W_EMD_C       1.2f
#define LOG2E_C       1.4426950408889634f
#define LN2_LN9_C     0.31546487678572877f

#define AWF (ALPHA_C * W_FAR_C)
#define AWT (ALPHA_C * W_TAIL_C)
#define AWL (ALPHA_C * W_LPEAK_C)
#define AWE (ALPHA_C * W_EMD_C)

__device__ float        g_partials[NBLK];
__device__ unsigned int g_count = 0;

__device__ __forceinline__ float f_ex2(float x){ float r; asm("ex2.approx.ftz.f32 %0, %1;" : "=f"(r) : "f"(x)); return r; }
__device__ __forceinline__ float f_lg2(float x){ float r; asm("lg2.approx.ftz.f32 %0, %1;" : "=f"(r) : "f"(x)); return r; }
__device__ __forceinline__ float f_rcp(float x){ float r; asm("rcp.approx.ftz.f32 %0, %1;" : "=f"(r) : "f"(x)); return r; }

__device__ __forceinline__ uint32_t smem_u32(const void* p) {
    uint32_t a;
    asm("{ .reg .u64 t; cvta.to.shared.u64 t, %1; cvt.u32.u64 %0, t; }" : "=r"(a) : "l"(p));
    return a;
}

#define MBAR_INIT(bar, cnt) \
    asm volatile("mbarrier.init.shared.b64 [%0], %1;" :: "r"(bar), "r"(cnt) : "memory")
#define MBAR_EXPECT_TX(bar, bytes) \
    asm volatile("mbarrier.arrive.expect_tx.shared.b64 _, [%0], %1;" :: "r"(bar), "r"(bytes) : "memory")
#define MBAR_WAIT(bar, ph) do {                                                   \
    asm volatile("{\n\t.reg .pred P;\n"                                           \
        "W_%=:\n\t"                                                               \
        "mbarrier.try_wait.parity.acquire.cta.shared::cta.b64 P, [%0], %1, 0x989680;\n\t" \
        "@P bra D_%=;\n\t"                                                        \
        "bra W_%=;\n"                                                             \
        "D_%=:\n\t}"                                                              \
        :: "r"(bar), "r"(ph) : "memory");                                         \
} while (0)
#define BULK_CP(dst, src, bytes, bar) \
    asm volatile("cp.async.bulk.shared::cta.global.mbarrier::complete_tx::bytes [%0], [%1], %2, [%3];" \
        :: "r"(dst), "l"(src), "r"(bytes), "r"(bar) : "memory")

__device__ __forceinline__ float cw_of(int k) {
    const float cw[KCLS] = {
        3.0f/95.0f, 7.0f/95.0f, 10.0f/95.0f, 10.0f/95.0f, 10.0f/95.0f,
        10.0f/95.0f, 10.0f/95.0f, 10.0f/95.0f, 25.0f/95.0f };
    return cw[k];
}

__device__ __forceinline__ float row_loss(const float* __restrict__ lrow, int y,
                                          const float* __restrict__ s_ccw) {
    const float fy = (float)y;
    float E = 0.0f, Q = 0.0f, A = 0.0f, tail = 0.0f, ef = 0.0f;

#pragma unroll
    for (int k = 0; k < KCLS; ++k) {
        float l = lrow[k];
        float e = f_ex2(l * LOG2E_C);                 // exp(l_k)
        E += e;                                        // prefix; E_8 == S
        float u = cw_of(k) * E;                        // FMUL imm
        Q = fmaf(u, E, Q);                             // sum cw_k E_k^2
        float d  = (float)k - fy;                      // shared
        float le = __saturatef(1.0f - d);              // 1 iff k<=y
        A = fmaf(le, u, A);
        float s  = fabsf(d) - 1.0f;                    // |d|-1 (abs modifier)
        float c  = fmaxf(s, 0.0f);
        float h  = e * c;                              // shared far/tail
        ef = fmaxf(ef, fminf(h, e));                   // e*min(c,1) = min(ec,e)
        tail = fmaf(h, c * c, tail);                   // e*(d-1)^3 far
    }

    float invS = f_rcp(E);
    float ty   = lrow[y] * LOG2E_C;
    float py   = f_ex2(ty) * invS;
    float nllN = (f_lg2(E) - ty) * LN2_LN9_C;

    int yl = (y > 0) ? y - 1 : 0;
    int yr = (y < KCLS - 1) ? y + 1 : KCLS - 1;
    float el = f_ex2(lrow[yl] * LOG2E_C) * __saturatef(fy);
    float er = f_ex2(lrow[yr] * LOG2E_C) * __saturatef(8.0f - fy);
    float en = fmaxf(el, er);

    float farm  = fmaxf(fmaf(ef, invS, DELTA_FAR_C   - py), 0.0f);
    float lpeak = fmaxf(fmaf(en, invS, PROB_MARGIN_C - py), 0.0f);
    float emd   = fmaf(Q, invS * invS, fmaf(-2.0f * A, invS, s_ccw[y]));

    float r = fmaf(AWF, farm, nllN);
    r = fmaf(AWT, tail * invS, r);
    r = fmaf(AWL, lpeak, r);
    r = fmaf(AWE, emd, r);
    return r;
}

__global__ __launch_bounds__(NTHREADS, 6)
void opcel_pipe(const float* __restrict__ logits,
                const int*   __restrict__ y,
                float*       __restrict__ out,
                int B, int nblocks) {
    __shared__ __align__(16) float s_log[NSTAGES][TILE * KCLS];  /* 2x9KB */
    __shared__ __align__(16) int   s_y[NSTAGES][TILE];           /* 2x1KB */
    __shared__ __align__(8)  unsigned long long s_bar[NSTAGES];
    __shared__ float s_ccw[KCLS];
    __shared__ float s_red[NTHREADS / 32];
    __shared__ int   s_last;

    const int tid = threadIdx.x;
    const int bid = blockIdx.x;

    if (tid < KCLS) {
        const float ccw[KCLS] = {
            3.0f/95.0f, 10.0f/95.0f, 20.0f/95.0f, 30.0f/95.0f, 40.0f/95.0f,
            50.0f/95.0f, 60.0f/95.0f, 70.0f/95.0f, 1.0f };
        s_ccw[tid] = ccw[tid];
    }

    const uint32_t bar0 = smem_u32(&s_bar[0]);
    const uint32_t bar1 = smem_u32(&s_bar[1]);
    const uint32_t d_log0 = smem_u32(&s_log[0][0]);
    const uint32_t d_log1 = smem_u32(&s_log[1][0]);
    const uint32_t d_y0   = smem_u32(&s_y[0][0]);
    const uint32_t d_y1   = smem_u32(&s_y[1][0]);

    if (tid == 0) { MBAR_INIT(bar0, 1); MBAR_INIT(bar1, 1); }
    __syncthreads();

    const int ntiles = B / TILE;
    int my_n = 0;
    for (long long t = bid; t < ntiles; t += nblocks) ++my_n;

    if (my_n > 0 && tid == 0) {
        long long t0 = bid;
        MBAR_EXPECT_TX(bar0, TX_BYTES);
        BULK_CP(d_log0, (const void*)(logits + t0 * (TILE * KCLS)), LOG_BYTES, bar0);
        BULK_CP(d_y0,   (const void*)(y + t0 * TILE),               Y_BYTES,  bar0);
    }

    float acc = 0.0f;
    int ph0 = 0, ph1 = 0;

    for (int j = 0; j < my_n; ++j) {
        const int s = j & 1;
        if (tid == 0 && (j + 1) < my_n) {
            long long tn = (long long)bid + (long long)(j + 1) * nblocks;
            if (s == 0) {
                MBAR_EXPECT_TX(bar1, TX_BYTES);
                BULK_CP(d_log1, (const void*)(logits + tn * (TILE * KCLS)), LOG_BYTES, bar1);
                BULK_CP(d_y1,   (const void*)(y + tn * TILE),               Y_BYTES,  bar1);
            } else {
                MBAR_EXPECT_TX(bar0, TX_BYTES);
                BULK_CP(d_log0, (const void*)(logits + tn * (TILE * KCLS)), LOG_BYTES, bar0);
                BULK_CP(d_y0,   (const void*)(y + tn * TILE),               Y_BYTES,  bar0);
            }
        }

        if (s == 0) { MBAR_WAIT(bar0, ph0); ph0 ^= 1; }
        else        { MBAR_WAIT(bar1, ph1); ph1 ^= 1; }

        acc += row_loss(s_log[s] + tid * KCLS, s_y[s][tid], s_ccw);
        __syncthreads();                 /* all lanes done reading stage s */
    }

    // Residue rows (B % TILE) -> block 0, direct global reads.
    if (bid == 0) {
        for (int r = ntiles * TILE + tid; r < B; r += NTHREADS)
            acc += row_loss(logits + (long long)r * KCLS, __ldg(&y[r]), s_ccw);
    }

    // Block reduction
#pragma unroll
    for (int off = 16; off > 0; off >>= 1)
        acc += __shfl_down_sync(0xFFFFFFFFu, acc, off);
    int lane = tid & 31, wid = tid >> 5;
    if (lane == 0) s_red[wid] = acc;
    __syncthreads();
    if (tid == 0) {
        float v = 0.0f;
#pragma unroll
        for (int w = 0; w < NTHREADS / 32; ++w) v += s_red[w];
        g_partials[bid] = v;
        __threadfence();
        unsigned int t = atomicAdd(&g_count, 1u);
        s_last = (t == (unsigned int)(nblocks - 1));
    }
    __syncthreads();

    // Last block: deterministic final reduction in double
    if (s_last) {
        double d = 0.0;
        for (int i = tid; i < nblocks; i += NTHREADS)
            d += (double)g_partials[i];
#pragma unroll
        for (int off = 16; off > 0; off >>= 1)
            d += __shfl_down_sync(0xFFFFFFFFu, d, off);

        __shared__ double s_d[NTHREADS / 32];
        if (lane == 0) s_d[wid] = d;
        __syncthreads();
        if (tid == 0) {
            double tot = 0.0;
#pragma unroll
            for (int w = 0; w < NTHREADS / 32; ++w) tot += s_d[w];
            out[0] = (float)(tot / (double)B);
            g_count = 0;   /* self-reset for graph replay */
        }
    }
}

extern "C" void kernel_launch(void* const* d_in, const int* in_sizes, int n_in,
                              void* d_out, int out_size) {
    const float* logits = (const float*)d_in[0];
    const int*   y      = (const int*)d_in[1];
    float* out = (float*)d_out;
    int B = in_sizes[1];

    int ntiles = B / TILE;
    int nblocks = NBLK;
    if (nblocks > ntiles && ntiles > 0) nblocks = ntiles;
    if (nblocks < 1) nblocks = 1;

    opcel_pipe<<<nblocks, NTHREADS>>>(logits, y, out, B, nblocks);
}

// round 11
// speedup vs baseline: 1.0847x; 1.0847x over previous
#include <cuda_runtime.h>
#include <cuda_bf16.h>
#include <cstdint>

// ---------------------------------------------------------------------------
// OrdinalPeakedCELoss — persistent double-buffered pipeline, v3.
//  R10 post-mortem: TILE=256 regression (tile overhead per row doubled);
//  issue ~79% both rounds -> instruction-count bound. v3 = R9 skeleton
//  (TILE=512, 2 rows/thread, 2 stages, 740 blocks) + instruction diet:
//   * no py: farm/lpeak on (ef-ey), (en-ey) scaled once by invS
//   * padded tile (+4 floats, zeroed guards) -> neighbor reads without clamps
//   * R10 lean per-class math (shared d/|d|-1, h=e*c for far&tail)
//  Deterministic: fixed tile->block map, fixed order, last-block double sum.
// ---------------------------------------------------------------------------

#define KCLS 9
#define NTHREADS 256
#define TILE 512
#define ROWS_PT 2
#define NSTAGES 2
#define PAD 4                                    /* guard floats each side  */
#define LOG_FLOATS (TILE * KCLS)                 /* 4608 */
#define LOG_BYTES (LOG_FLOATS * 4)               /* 18432 */
#define Y_BYTES   (TILE * 4)                     /* 2048  */
#define TX_BYTES  (LOG_BYTES + Y_BYTES)
#define NBLK 740

#define ALPHA_C       0.4f
#define W_FAR_C       7.0f
#define DELTA_FAR_C   0.15f
#define W_TAIL_C      9.0f
#define W_LPEAK_C     12.0f
#define PROB_MARGIN_C 0.35f
#define W_EMD_C       1.2f
#define LOG2E_C       1.4426950408889634f
#define LN2_LN9_C     0.31546487678572877f

#define AWF (ALPHA_C * W_FAR_C)
#define AWT (ALPHA_C * W_TAIL_C)
#define AWL (ALPHA_C * W_LPEAK_C)
#define AWE (ALPHA_C * W_EMD_C)

__device__ float        g_partials[NBLK];
__device__ unsigned int g_count = 0;

__device__ __forceinline__ float f_ex2(float x){ float r; asm("ex2.approx.ftz.f32 %0, %1;" : "=f"(r) : "f"(x)); return r; }
__device__ __forceinline__ float f_lg2(float x){ float r; asm("lg2.approx.ftz.f32 %0, %1;" : "=f"(r) : "f"(x)); return r; }
__device__ __forceinline__ float f_rcp(float x){ float r; asm("rcp.approx.ftz.f32 %0, %1;" : "=f"(r) : "f"(x)); return r; }

__device__ __forceinline__ uint32_t smem_u32(const void* p) {
    uint32_t a;
    asm("{ .reg .u64 t; cvta.to.shared.u64 t, %1; cvt.u32.u64 %0, t; }" : "=r"(a) : "l"(p));
    return a;
}

#define MBAR_INIT(bar, cnt) \
    asm volatile("mbarrier.init.shared.b64 [%0], %1;" :: "r"(bar), "r"(cnt) : "memory")
#define MBAR_EXPECT_TX(bar, bytes) \
    asm volatile("mbarrier.arrive.expect_tx.shared.b64 _, [%0], %1;" :: "r"(bar), "r"(bytes) : "memory")
#define MBAR_WAIT(bar, ph) do {                                                   \
    asm volatile("{\n\t.reg .pred P;\n"                                           \
        "W_%=:\n\t"                                                               \
        "mbarrier.try_wait.parity.acquire.cta.shared::cta.b64 P, [%0], %1, 0x989680;\n\t" \
        "@P bra D_%=;\n\t"                                                        \
        "bra W_%=;\n"                                                             \
        "D_%=:\n\t}"                                                              \
        :: "r"(bar), "r"(ph) : "memory");                                         \
} while (0)
#define BULK_CP(dst, src, bytes, bar) \
    asm volatile("cp.async.bulk.shared::cta.global.mbarrier::complete_tx::bytes [%0], [%1], %2, [%3];" \
        :: "r"(dst), "l"(src), "r"(bytes), "r"(bar) : "memory")

__device__ __forceinline__ float cw_of(int k) {
    const float cw[KCLS] = {
        3.0f/95.0f, 7.0f/95.0f, 10.0f/95.0f, 10.0f/95.0f, 10.0f/95.0f,
        10.0f/95.0f, 10.0f/95.0f, 10.0f/95.0f, 25.0f/95.0f };
    return cw[k];
}

// Hot path: lrow must be readable at [-1] and [9] (padded tile guarantees it;
// out-of-row values are finite and masked to zero).
__device__ __forceinline__ float row_loss(const float* __restrict__ lrow, int y,
                                          const float* __restrict__ s_ccw) {
    const float fy  = (float)y;
    const float fy1 = fy + 1.0f;

    float E = 0.0f, Q = 0.0f, A = 0.0f, tail = 0.0f, ef = 0.0f;

#pragma unroll
    for (int k = 0; k < KCLS; ++k) {
        float e = f_ex2(lrow[k] * LOG2E_C);            // exp(l_k)
        E += e;                                         // prefix; E_8 == S
        float u = cw_of(k) * E;                         // FMUL imm
        Q = fmaf(u, E, Q);                              // sum cw_k E_k^2
        float le = __saturatef(fy1 - (float)k);         // 1 iff k<=y
        A = fmaf(le, u, A);
        float s = fabsf((float)k - fy) - 1.0f;          // |d|-1
        float c = fmaxf(s, 0.0f);
        float h = e * c;
        ef = fmaxf(ef, fminf(h, e));                    // e*min(c,1)
        tail = fmaf(h, c * c, tail);                    // e*(|d|-1)^3
    }

    float invS = f_rcp(E);
    float ty = lrow[y] * LOG2E_C;
    float ey = f_ex2(ty);
    float el = f_ex2(lrow[y - 1] * LOG2E_C) * __saturatef(fy);         // 0 at y=0
    float er = f_ex2(lrow[y + 1] * LOG2E_C) * __saturatef(8.0f - fy);  // 0 at y=8
    float en = fmaxf(el, er);

    float farm  = fmaxf(fmaf(ef - ey, invS, DELTA_FAR_C),   0.0f);
    float lpeak = fmaxf(fmaf(en - ey, invS, PROB_MARGIN_C), 0.0f);
    float emd   = fmaf(Q, invS * invS, fmaf(-2.0f * A, invS, s_ccw[y]));

    float r = (f_lg2(E) - ty) * LN2_LN9_C;              // nll / ln 9
    r = fmaf(AWF, farm, r);
    r = fmaf(AWT, tail * invS, r);
    r = fmaf(AWL, lpeak, r);
    r = fmaf(AWE, emd, r);
    return r;
}

// Residue path (rare): clamped indices, direct global reads.
__device__ __noinline__ float row_loss_global(const float* __restrict__ g, int y,
                                              const float* __restrict__ s_ccw) {
    const float fy = (float)y;
    float E = 0.0f, Q = 0.0f, A = 0.0f, tail = 0.0f, ef = 0.0f;
    float lv[KCLS];
#pragma unroll
    for (int k = 0; k < KCLS; ++k) lv[k] = __ldg(&g[k]);
#pragma unroll
    for (int k = 0; k < KCLS; ++k) {
        float e = f_ex2(lv[k] * LOG2E_C);
        E += e;
        float u = cw_of(k) * E;
        Q = fmaf(u, E, Q);
        float le = __saturatef(fy + 1.0f - (float)k);
        A = fmaf(le, u, A);
        float s = fabsf((float)k - fy) - 1.0f;
        float c = fmaxf(s, 0.0f);
        float h = e * c;
        ef = fmaxf(ef, fminf(h, e));
        tail = fmaf(h, c * c, tail);
    }
    float invS = f_rcp(E);
    int yl = (y > 0) ? y - 1 : 0;
    int yr = (y < KCLS - 1) ? y + 1 : KCLS - 1;
    float ty = lv[y] * LOG2E_C;
    float ey = f_ex2(ty);
    float el = f_ex2(lv[yl] * LOG2E_C) * __saturatef(fy);
    float er = f_ex2(lv[yr] * LOG2E_C) * __saturatef(8.0f - fy);
    float en = fmaxf(el, er);
    float farm  = fmaxf(fmaf(ef - ey, invS, DELTA_FAR_C),   0.0f);
    float lpeak = fmaxf(fmaf(en - ey, invS, PROB_MARGIN_C), 0.0f);
    float emd   = fmaf(Q, invS * invS, fmaf(-2.0f * A, invS, s_ccw[y]));
    float r = (f_lg2(E) - ty) * LN2_LN9_C;
    r = fmaf(AWF, farm, r);
    r = fmaf(AWT, tail * invS, r);
    r = fmaf(AWL, lpeak, r);
    r = fmaf(AWE, emd, r);
    return r;
}

__global__ __launch_bounds__(NTHREADS, 5)
void opcel_pipe(const float* __restrict__ logits,
                const int*   __restrict__ y,
                float*       __restrict__ out,
                int B, int nblocks) {
    /* +2*PAD guard floats per stage; bulk copy lands at +PAD (16B aligned) */
    __shared__ __align__(16) float s_log[NSTAGES][LOG_FLOATS + 2 * PAD];
    __shared__ __align__(16) int   s_y[NSTAGES][TILE];
    __shared__ __align__(8)  unsigned long long s_bar[NSTAGES];
    __shared__ float s_ccw[KCLS];
    __shared__ float s_red[NTHREADS / 32];
    __shared__ int   s_last;

    const int tid = threadIdx.x;
    const int bid = blockIdx.x;

    if (tid < KCLS) {
        const float ccw[KCLS] = {
            3.0f/95.0f, 10.0f/95.0f, 20.0f/95.0f, 30.0f/95.0f, 40.0f/95.0f,
            50.0f/95.0f, 60.0f/95.0f, 70.0f/95.0f, 1.0f };
        s_ccw[tid] = ccw[tid];
    }
    // Zero the guard pads once (never touched by bulk copies afterwards).
    if (tid < PAD) {
#pragma unroll
        for (int s = 0; s < NSTAGES; ++s) {
            s_log[s][tid] = 0.0f;
            s_log[s][PAD + LOG_FLOATS + tid] = 0.0f;
        }
    }

    const uint32_t bar0 = smem_u32(&s_bar[0]);
    const uint32_t bar1 = smem_u32(&s_bar[1]);
    const uint32_t d_log0 = smem_u32(&s_log[0][PAD]);
    const uint32_t d_log1 = smem_u32(&s_log[1][PAD]);
    const uint32_t d_y0   = smem_u32(&s_y[0][0]);
    const uint32_t d_y1   = smem_u32(&s_y[1][0]);

    if (tid == 0) { MBAR_INIT(bar0, 1); MBAR_INIT(bar1, 1); }
    __syncthreads();

    const int ntiles = B / TILE;
    int my_n = 0;
    for (long long t = bid; t < ntiles; t += nblocks) ++my_n;

    if (my_n > 0 && tid == 0) {
        long long t0 = bid;
        MBAR_EXPECT_TX(bar0, TX_BYTES);
        BULK_CP(d_log0, (const void*)(logits + t0 * (TILE * KCLS)), LOG_BYTES, bar0);
        BULK_CP(d_y0,   (const void*)(y + t0 * TILE),               Y_BYTES,  bar0);
    }

    float acc = 0.0f;
    int ph0 = 0, ph1 = 0;

    for (int j = 0; j < my_n; ++j) {
        const int s = j & 1;
        if (tid == 0 && (j + 1) < my_n) {
            long long tn = (long long)bid + (long long)(j + 1) * nblocks;
            if (s == 0) {
                MBAR_EXPECT_TX(bar1, TX_BYTES);
                BULK_CP(d_log1, (const void*)(logits + tn * (TILE * KCLS)), LOG_BYTES, bar1);
                BULK_CP(d_y1,   (const void*)(y + tn * TILE),               Y_BYTES,  bar1);
            } else {
                MBAR_EXPECT_TX(bar0, TX_BYTES);
                BULK_CP(d_log0, (const void*)(logits + tn * (TILE * KCLS)), LOG_BYTES, bar0);
                BULK_CP(d_y0,   (const void*)(y + tn * TILE),               Y_BYTES,  bar0);
            }
        }

        if (s == 0) { MBAR_WAIT(bar0, ph0); ph0 ^= 1; }
        else        { MBAR_WAIT(bar1, ph1); ph1 ^= 1; }

        const float* lg = &s_log[s][PAD];
        const int*   yt = s_y[s];
#pragma unroll
        for (int jj = 0; jj < ROWS_PT; ++jj) {
            int lr = tid + jj * NTHREADS;       /* stride-9-word rows: conflict-free */
            acc += row_loss(lg + lr * KCLS, yt[lr], s_ccw);
        }
        __syncthreads();                        /* all lanes done reading stage s */
    }

    // Residue rows (B % TILE) -> block 0, direct global reads.
    if (bid == 0) {
        for (int r = ntiles * TILE + tid; r < B; r += NTHREADS)
            acc += row_loss_global(logits + (long long)r * KCLS, __ldg(&y[r]), s_ccw);
    }

    // Block reduction
#pragma unroll
    for (int off = 16; off > 0; off >>= 1)
        acc += __shfl_down_sync(0xFFFFFFFFu, acc, off);
    int lane = tid & 31, wid = tid >> 5;
    if (lane == 0) s_red[wid] = acc;
    __syncthreads();
    if (tid == 0) {
        float v = 0.0f;
#pragma unroll
        for (int w = 0; w < NTHREADS / 32; ++w) v += s_red[w];
        g_partials[bid] = v;
        __threadfence();
        unsigned int t = atomicAdd(&g_count, 1u);
        s_last = (t == (unsigned int)(nblocks - 1));
    }
    __syncthreads();

    // Last block: deterministic final reduction in double
    if (s_last) {
        double d = 0.0;
        for (int i = tid; i < nblocks; i += NTHREADS)
            d += (double)g_partials[i];
#pragma unroll
        for (int off = 16; off > 0; off >>= 1)
            d += __shfl_down_sync(0xFFFFFFFFu, d, off);

        __shared__ double s_d[NTHREADS / 32];
        if (lane == 0) s_d[wid] = d;
        __syncthreads();
        if (tid == 0) {
            double tot = 0.0;
#pragma unroll
            for (int w = 0; w < NTHREADS / 32; ++w) tot += s_d[w];
            out[0] = (float)(tot / (double)B);
            g_count = 0;   /* self-reset for graph replay */
        }
    }
}

extern "C" void kernel_launch(void* const* d_in, const int* in_sizes, int n_in,
                              void* d_out, int out_size) {
    const float* logits = (const float*)d_in[0];
    const int*   y      = (const int*)d_in[1];
    float* out = (float*)d_out;
    int B = in_sizes[1];

    int ntiles = B / TILE;
    int nblocks = NBLK;
    if (nblocks > ntiles && ntiles > 0) nblocks = ntiles;
    if (nblocks < 1) nblocks = 1;

    opcel_pipe<<<nblocks, NTHREADS>>>(logits, y, out, B, nblocks);
}